// round 9
// baseline (speedup 1.0000x reference)
#include <cuda_runtime.h>
#include <cuda_fp16.h>
#include <cstdint>
#include <cstddef>

#define DIM 1024
#define NH 16
#define HD 64
#define NB 8
#define LQ 512
#define LKK 1024
#define MQ (NB*LQ)      // 4096
#define MK (NB*LKK)     // 8192
#define EPSV 1e-5f
#define QSCALE 0.125f
#define WUP 32.0f
#define WINV (1.0f/32.0f)

// ------------------------- scratch -------------------------
__device__ float g_att[(size_t)MQ * DIM];

__device__ __half g_tAhi[(size_t)MQ * DIM];          // text fp16
__device__ __half g_tVhi[(size_t)MK * DIM];          // vision fp16
__device__ __half g_tWhi[(size_t)3*DIM*DIM];         // 32*in_proj_w fp16
__device__ __half g_tOhi[(size_t)DIM*DIM];           // 32*out_w fp16
__device__ __half g_Qhi[(size_t)MQ * DIM];           // scaled Q
__device__ __half g_Khi[(size_t)MK * DIM];
__device__ __half g_Vhi[(size_t)MK * DIM];
__device__ __half g_Chi[(size_t)MQ * DIM];           // ctx

// ------------------------- helpers -------------------------
__device__ __forceinline__ uint32_t smem_to_u32(const void* p) {
    uint32_t a;
    asm("{ .reg .u64 t; cvta.to.shared.u64 t, %1; cvt.u32.u64 %0, t; }" : "=r"(a) : "l"(p));
    return a;
}
__device__ __forceinline__ void ldsm_x4(uint32_t* r, uint32_t addr) {
    asm volatile("ldmatrix.sync.aligned.m8n8.x4.shared.b16 {%0,%1,%2,%3}, [%4];"
        : "=r"(r[0]), "=r"(r[1]), "=r"(r[2]), "=r"(r[3]) : "r"(addr));
}
__device__ __forceinline__ void ldsm_x4_t(uint32_t* r, uint32_t addr) {
    asm volatile("ldmatrix.sync.aligned.m8n8.x4.trans.shared.b16 {%0,%1,%2,%3}, [%4];"
        : "=r"(r[0]), "=r"(r[1]), "=r"(r[2]), "=r"(r[3]) : "r"(addr));
}
__device__ __forceinline__ void mma16816(float* d, const uint32_t* a, const uint32_t* b) {
    asm volatile("mma.sync.aligned.m16n8k16.row.col.f32.f16.f16.f32 "
        "{%0,%1,%2,%3}, {%4,%5,%6,%7}, {%8,%9}, {%0,%1,%2,%3};"
        : "+f"(d[0]), "+f"(d[1]), "+f"(d[2]), "+f"(d[3])
        : "r"(a[0]), "r"(a[1]), "r"(a[2]), "r"(a[3]), "r"(b[0]), "r"(b[1]));
}
__device__ __forceinline__ uint32_t h2bits(float a, float b) {
    __half2 h = __floats2half2_rn(a, b);
    return *(uint32_t*)&h;
}
__device__ __forceinline__ void cp16(uint32_t saddr, const void* g) {
    asm volatile("cp.async.cg.shared.global [%0], [%1], 16;" :: "r"(saddr), "l"(g));
}
#define CP_COMMIT() asm volatile("cp.async.commit_group;" ::: "memory")
#define CP_WAIT0()  asm volatile("cp.async.wait_group 0;" ::: "memory")
#define CP_WAIT1()  asm volatile("cp.async.wait_group 1;" ::: "memory")

// ------------------------- conversion -------------------------
__global__ __launch_bounds__(256) void cvt_hi(const float4* __restrict__ x,
                                              uint32_t* __restrict__ hi,
                                              float scale, int n4)
{
    int i = blockIdx.x * blockDim.x + threadIdx.x;
    if (i >= n4) return;
    float4 v = x[i];
    hi[2 * i]     = h2bits(v.x * scale, v.y * scale);
    hi[2 * i + 1] = h2bits(v.z * scale, v.w * scale);
}

// ------------------------- mma.sync fp16 GEMM (128x256 tile, 3-stage) -------------------------
// C = A @ W^T (+bias/res). A fp16; W = 32*W fp16; acc * 1/32 in epilogue.
// KC=32; stage = A 8KB + W 16KB = 24KB; 3 stages = 72KB. Warp tile 64x64.
#define GA_TILE 8192
#define GW_TILE 16384
#define GSTAGE  (GA_TILE + GW_TILE)
#define GSM_TOTAL (3 * GSTAGE)

template<int MODE>
__global__ __launch_bounds__(256, 1) void gemm_mma(
    const __half* __restrict__ Ahi, const __half* __restrict__ Whi,
    const float* __restrict__ bias, const float* __restrict__ res,
    float* __restrict__ C,
    __half* __restrict__ h0, __half* __restrict__ h1,
    int M, int N, int K)
{
    extern __shared__ char sm[];
    const uint32_t sb = smem_to_u32(sm);

    const int tid  = threadIdx.x;
    const int wid  = tid >> 5;
    const int lane = tid & 31;
    const int bm = blockIdx.y * 128;
    const int bn = blockIdx.x * 256;
    const int m0 = (wid >> 2) * 64;
    const int n0 = (wid & 3) * 64;

    // loader slots: A 2/thread (128 rows x 4 slots), W 4/thread (256 rows x 4 slots)
    int arow_g[2], asl[2], aoff[2];
#pragma unroll
    for (int i = 0; i < 2; i++) {
        int u = tid + i * 256;
        arow_g[i] = u >> 2;
        asl[i]    = u & 3;
        aoff[i]   = arow_g[i] * 64 + ((asl[i] << 4) ^ (((arow_g[i] >> 1) & 3) << 4));
    }
    int wrow_g[4], wsl[4], woff[4];
#pragma unroll
    for (int i = 0; i < 4; i++) {
        int u = tid + i * 256;
        wrow_g[i] = u >> 2;
        wsl[i]    = u & 3;
        woff[i]   = wrow_g[i] * 64 + ((wsl[i] << 4) ^ (((wrow_g[i] >> 1) & 3) << 4));
    }

    const int arow_l = lane & 15;
    const int a_hi   = lane >> 4;
    const int brow_l = (lane & 7) + ((lane & 16) ? 8 : 0);
    const int b_hi   = (lane & 8) ? 1 : 0;
    const int gid = lane >> 2, tig = lane & 3;

    float acc[4][8][4];
#pragma unroll
    for (int i = 0; i < 4; i++)
#pragma unroll
        for (int j = 0; j < 8; j++)
#pragma unroll
            for (int l = 0; l < 4; l++) acc[i][j][l] = 0.f;

    const int nch = K >> 5;

    // prologue: chunks 0,1
#pragma unroll
    for (int c0 = 0; c0 < 2; c0++) {
        const uint32_t base = sb + c0 * GSTAGE;
        const int coff = c0 * 32;
#pragma unroll
        for (int i = 0; i < 2; i++)
            cp16(base + aoff[i], Ahi + (size_t)(bm + arow_g[i]) * K + coff + asl[i] * 8);
#pragma unroll
        for (int i = 0; i < 4; i++)
            cp16(base + GA_TILE + woff[i], Whi + (size_t)(bn + wrow_g[i]) * K + coff + wsl[i] * 8);
        CP_COMMIT();
    }

    int stg = 0;
    for (int c = 0; c < nch; c++) {
        if (c + 1 < nch) { CP_WAIT1(); } else { CP_WAIT0(); }
        __syncthreads();
        if (c + 2 < nch) {
            int ns = stg + 2; if (ns >= 3) ns -= 3;
            const uint32_t base = sb + ns * GSTAGE;
            const int coff = (c + 2) * 32;
#pragma unroll
            for (int i = 0; i < 2; i++)
                cp16(base + aoff[i], Ahi + (size_t)(bm + arow_g[i]) * K + coff + asl[i] * 8);
#pragma unroll
            for (int i = 0; i < 4; i++)
                cp16(base + GA_TILE + woff[i], Whi + (size_t)(bn + wrow_g[i]) * K + coff + wsl[i] * 8);
            CP_COMMIT();
        }
        const uint32_t tb = sb + stg * GSTAGE;
#pragma unroll
        for (int ks = 0; ks < 2; ks++) {
            uint32_t ah[4][4];
#pragma unroll
            for (int mf = 0; mf < 4; mf++) {
                const int row = m0 + mf * 16 + arow_l;
                const int sl  = ks * 2 + a_hi;
                ldsm_x4(ah[mf], tb + row * 64 + ((sl << 4) ^ (((row >> 1) & 3) << 4)));
            }
            uint32_t bh[4][4];
#pragma unroll
            for (int nf4 = 0; nf4 < 4; nf4++) {
                const int row = n0 + nf4 * 16 + brow_l;
                const int sl  = ks * 2 + b_hi;
                ldsm_x4(bh[nf4], tb + GA_TILE + row * 64 + ((sl << 4) ^ (((row >> 1) & 3) << 4)));
            }
#pragma unroll
            for (int mf = 0; mf < 4; mf++)
#pragma unroll
                for (int nf4 = 0; nf4 < 4; nf4++)
#pragma unroll
                    for (int half = 0; half < 2; half++)
                        mma16816(acc[mf][nf4 * 2 + half], ah[mf], &bh[nf4][half * 2]);
        }
        stg++; if (stg == 3) stg = 0;
    }

    // ---- epilogue ----
#pragma unroll
    for (int mf = 0; mf < 4; mf++) {
        const int mrow0 = bm + m0 + mf * 16 + gid;
#pragma unroll
        for (int nf = 0; nf < 8; nf++) {
            const int col = bn + n0 + nf * 8 + tig * 2;
            const float2 bia = *(const float2*)&bias[col];
            float* d = acc[mf][nf];
            float v00 = d[0] * WINV + bia.x, v01 = d[1] * WINV + bia.y;
            float v10 = d[2] * WINV + bia.x, v11 = d[3] * WINV + bia.y;
            if (MODE == 0) {
                const size_t i0 = (size_t)mrow0 * N + col;
                const size_t i1 = (size_t)(mrow0 + 8) * N + col;
                if (res) {
                    float2 r0 = *(const float2*)&res[i0];
                    float2 r1 = *(const float2*)&res[i1];
                    v00 += r0.x; v01 += r0.y; v10 += r1.x; v11 += r1.y;
                }
                *(float2*)&C[i0] = make_float2(v00, v01);
                *(float2*)&C[i1] = make_float2(v10, v11);
            } else if (MODE == 1) {
                v00 *= QSCALE; v01 *= QSCALE; v10 *= QSCALE; v11 *= QSCALE;
                const size_t i0 = (size_t)mrow0 * DIM + col;
                const size_t i1 = (size_t)(mrow0 + 8) * DIM + col;
                *(uint32_t*)&h0[i0] = h2bits(v00, v01);
                *(uint32_t*)&h0[i1] = h2bits(v10, v11);
            } else {
                __half* H = h0;
                int cc = col;
                if (col >= DIM) { H = h1; cc = col - DIM; }
                const size_t i0 = (size_t)mrow0 * DIM + cc;
                const size_t i1 = (size_t)(mrow0 + 8) * DIM + cc;
                *(uint32_t*)&H[i0] = h2bits(v00, v01);
                *(uint32_t*)&H[i1] = h2bits(v10, v11);
            }
        }
    }
}

// ------------------------- tensor-core attention (256-key chunks) -------------------------
#define SM_QH  131072
#define SM_KV0 135168
#define KV_BUF 32768           // 256 keys x 128B
#define ATTN_SMEM (SM_KV0 + 2 * KV_BUF)   // 200704

__global__ __launch_bounds__(256) void attn_mma(float* __restrict__ attnw)
{
    extern __shared__ char sm[];
    float* S = (float*)sm;
    const uint32_t sb = smem_to_u32(sm);

    const int tid  = threadIdx.x;
    const int wid  = tid >> 5;
    const int lane = tid & 31;
    const int b  = blockIdx.x >> 4;
    const int q0 = (blockIdx.x & 15) << 5;

    const int ms  = (wid >> 2) * 16;
    const int ns2 = (wid & 3) * 64;     // 64-key slice within 256-chunk
    const int nv0 = (wid & 3) * 16;

    const int arow_l = lane & 15;
    const int axor   = (arow_l & 7) << 4;
    const int akb    = (lane >> 4) * 16;
    const int brow_l = (lane & 7) + ((lane & 16) ? 8 : 0);
    const int bxor   = (lane & 7) << 4;
    const int bkb    = (lane & 8) ? 16 : 0;
    const int gid = lane >> 2, tig = lane & 3;

    // K/V 256-key chunk loader: 8 slots/thread (256 rows x 8 16B-slots)
    int krow[8], koff_s[8], kcu[8];
#pragma unroll
    for (int i = 0; i < 8; i++) {
        int u = tid + i * 256;
        krow[i] = u >> 3;
        kcu[i]  = u & 7;
        koff_s[i] = krow[i] * 128 + ((kcu[i] * 16) ^ ((krow[i] & 7) << 4));
    }
    const int qrow = tid >> 3, qcu = tid & 7;
    const int qoff = qrow * 128 + ((qcu * 16) ^ ((qrow & 7) << 4));

    const int vkey_l = ((lane >> 3) & 1) * 8 + (lane & 7);
    const int vdim   = nv0 + ((lane >> 4) ? 8 : 0);

    float awacc[4][32];
#pragma unroll
    for (int rr = 0; rr < 4; rr++)
#pragma unroll
        for (int j = 0; j < 32; j++) awacc[rr][j] = 0.f;

    for (int h = 0; h < NH; h++) {
        {
            size_t g = ((size_t)(b * LQ + q0 + qrow)) * DIM + h * HD + qcu * 8;
            *(uint4*)(sm + SM_QH + qoff) = *(const uint4*)(g_Qhi + g);
        }
        __syncthreads();

        // K chunk 0 -> buf 0
        {
#pragma unroll
            for (int i = 0; i < 8; i++) {
                size_t g = ((size_t)(b * LKK + krow[i])) * DIM + h * HD + kcu[i] * 8;
                cp16(sb + SM_KV0 + koff_s[i], g_Khi + g);
            }
            CP_COMMIT();
        }

        uint32_t qh[4][4];
#pragma unroll
        for (int ks = 0; ks < 4; ks++) {
            int koff = (ks * 32 + akb) ^ axor;
            ldsm_x4(qh[ks], sb + SM_QH + (ms + arow_l) * 128 + koff);
        }

        // ---- scores: 4 chunks of 256 keys ----
        for (int kc = 0; kc < 4; kc++) {
            CP_WAIT0();
            __syncthreads();
            if (kc < 3) {
                const uint32_t base = sb + SM_KV0 + ((kc + 1) & 1) * KV_BUF;
#pragma unroll
                for (int i = 0; i < 8; i++) {
                    size_t g = ((size_t)(b * LKK + (kc + 1) * 256 + krow[i])) * DIM + h * HD + kcu[i] * 8;
                    cp16(base + koff_s[i], g_Khi + g);
                }
                CP_COMMIT();
            }
            const uint32_t kb = sb + SM_KV0 + (kc & 1) * KV_BUF;
            float acc[8][4];
#pragma unroll
            for (int i = 0; i < 8; i++)
#pragma unroll
                for (int j = 0; j < 4; j++) acc[i][j] = 0.f;
#pragma unroll
            for (int ks = 0; ks < 4; ks++) {
                const int bkoff = (ks * 32 + bkb) ^ bxor;
                uint32_t bh[4][4];
#pragma unroll
                for (int np = 0; np < 4; np++)
                    ldsm_x4(bh[np], kb + (ns2 + np * 16 + brow_l) * 128 + bkoff);
#pragma unroll
                for (int np = 0; np < 4; np++)
#pragma unroll
                    for (int half = 0; half < 2; half++)
                        mma16816(acc[np * 2 + half], qh[ks], &bh[np][half * 2]);
            }
#pragma unroll
            for (int nf = 0; nf < 8; nf++) {
                const int col = kc * 256 + ns2 + nf * 8 + tig * 2;
                *(float2*)&S[(ms + gid) * LKK + col]     = make_float2(acc[nf][0], acc[nf][1]);
                *(float2*)&S[(ms + gid + 8) * LKK + col] = make_float2(acc[nf][2], acc[nf][3]);
            }
        }
        __syncthreads();

        // V chunk 0 -> buf 0 (overlaps softmax)
        {
#pragma unroll
            for (int i = 0; i < 8; i++) {
                size_t g = ((size_t)(b * LKK + krow[i])) * DIM + h * HD + kcu[i] * 8;
                cp16(sb + SM_KV0 + koff_s[i], g_Vhi + g);
            }
            CP_COMMIT();
        }

        // ---- fused softmax + register attnw + fp16 P ----
#pragma unroll
        for (int rr = 0; rr < 4; rr++) {
            const int r = wid * 4 + rr;
            float v[32];
            const float* src = &S[r * LKK + lane * 32];
#pragma unroll
            for (int j = 0; j < 8; j++) *(float4*)&v[j * 4] = *(const float4*)&src[j * 4];
            float mx = -1e30f;
#pragma unroll
            for (int j = 0; j < 32; j++) mx = fmaxf(mx, v[j]);
#pragma unroll
            for (int o = 16; o > 0; o >>= 1) mx = fmaxf(mx, __shfl_xor_sync(0xffffffffu, mx, o));
            float s = 0.f;
#pragma unroll
            for (int j = 0; j < 32; j++) { v[j] = __expf(v[j] - mx); s += v[j]; }
#pragma unroll
            for (int o = 16; o > 0; o >>= 1) s += __shfl_xor_sync(0xffffffffu, s, o);
            const float inv = 1.0f / s;
#pragma unroll
            for (int j = 0; j < 32; j++) v[j] *= inv;

#pragma unroll
            for (int j = 0; j < 32; j++) awacc[rr][j] += v[j];

            char* rb = sm + r * 4096;
            const int sw = (r & 7) << 4;
#pragma unroll
            for (int j = 0; j < 4; j++) {
                uint32_t h4[4];
#pragma unroll
                for (int p = 0; p < 4; p++)
                    h4[p] = h2bits(v[j * 8 + p * 2], v[j * 8 + p * 2 + 1]);
                const int off = ((lane * 4 + j) * 16) ^ sw;
                *(uint4*)(rb + off) = *(uint4*)h4;
            }
        }

        // ---- ctx = P @ V : 4 chunks of 256 keys ----
        float cacc[2][4];
#pragma unroll
        for (int g = 0; g < 2; g++)
#pragma unroll
            for (int l = 0; l < 4; l++) cacc[g][l] = 0.f;

        for (int kc = 0; kc < 4; kc++) {
            CP_WAIT0();
            __syncthreads();
            if (kc < 3) {
                const uint32_t base = sb + SM_KV0 + ((kc + 1) & 1) * KV_BUF;
#pragma unroll
                for (int i = 0; i < 8; i++) {
                    size_t g = ((size_t)(b * LKK + (kc + 1) * 256 + krow[i])) * DIM + h * HD + kcu[i] * 8;
                    cp16(base + koff_s[i], g_Vhi + g);
                }
                CP_COMMIT();
            }
            const uint32_t vb = sb + SM_KV0 + (kc & 1) * KV_BUF;
            const int mrow = ms + arow_l;
            const uint32_t pbase = sb + mrow * 4096;
            const int psw = (mrow & 7) << 4;
#pragma unroll
            for (int ks = 0; ks < 16; ks++) {
                const int poff = ((kc * 512 + ks * 32 + akb) ^ psw);
                uint32_t pah[4];
                ldsm_x4(pah, pbase + poff);
                const int key = ks * 16 + vkey_l;
                const uint32_t vaddr = vb + key * 128 + ((vdim * 2) ^ ((key & 7) << 4));
                uint32_t vh[4];
                ldsm_x4_t(vh, vaddr);
#pragma unroll
                for (int g = 0; g < 2; g++)
                    mma16816(cacc[g], pah, &vh[g * 2]);
            }
        }
#pragma unroll
        for (int g = 0; g < 2; g++) {
            const int col = h * HD + nv0 + g * 8 + tig * 2;
            const size_t i0 = ((size_t)(b * LQ + q0 + ms + gid)) * DIM + col;
            const size_t i1 = ((size_t)(b * LQ + q0 + ms + gid + 8)) * DIM + col;
            *(uint32_t*)&g_Chi[i0] = h2bits(cacc[g][0], cacc[g][1]);
            *(uint32_t*)&g_Chi[i1] = h2bits(cacc[g][2], cacc[g][3]);
        }
    }

    // ---- final attn_weights write (mean over heads) ----
    {
        const float invh = 1.0f / NH;
#pragma unroll
        for (int rr = 0; rr < 4; rr++) {
            float* aw = attnw + ((size_t)(b * LQ + q0 + wid * 4 + rr)) * LKK + lane * 32;
#pragma unroll
            for (int j = 0; j < 8; j++) {
                float4 p = make_float4(awacc[rr][j*4] * invh,   awacc[rr][j*4+1] * invh,
                                       awacc[rr][j*4+2] * invh, awacc[rr][j*4+3] * invh);
                *(float4*)&aw[j * 4] = p;
            }
        }
    }
}

// ------------------------- layernorm -------------------------
__global__ __launch_bounds__(256) void ln_kernel(
    const float* __restrict__ X, const float* __restrict__ gam,
    const float* __restrict__ bet, float* __restrict__ out)
{
    __shared__ float red[64];
    __shared__ float s_mu, s_rinv;
    const int r = blockIdx.x, tid = threadIdx.x;
    const float* x = X + (size_t)r * DIM;
    float4 v = *(const float4*)&x[tid * 4];
    float s  = v.x + v.y + v.z + v.w;
    float sq = v.x * v.x + v.y * v.y + v.z * v.z + v.w * v.w;
#pragma unroll
    for (int o = 16; o > 0; o >>= 1) {
        s  += __shfl_xor_sync(0xffffffffu, s, o);
        sq += __shfl_xor_sync(0xffffffffu, sq, o);
    }
    const int w = tid >> 5;
    if ((tid & 31) == 0) { red[w] = s; red[32 + w] = sq; }
    __syncthreads();
    if (tid == 0) {
        float S = 0, Q = 0;
        for (int i = 0; i < 8; i++) { S += red[i]; Q += red[32 + i]; }
        float mu = S * (1.0f / DIM);
        float var = Q * (1.0f / DIM) - mu * mu;
        s_mu = mu;
        s_rinv = rsqrtf(var + EPSV);
    }
    __syncthreads();
    const float mu = s_mu, rinv = s_rinv;
    float4 gg = *(const float4*)&gam[tid * 4];
    float4 bb = *(const float4*)&bet[tid * 4];
    float4 o;
    o.x = (v.x - mu) * rinv * gg.x + bb.x;
    o.y = (v.y - mu) * rinv * gg.y + bb.y;
    o.z = (v.z - mu) * rinv * gg.z + bb.z;
    o.w = (v.w - mu) * rinv * gg.w + bb.w;
    *(float4*)&out[(size_t)r * DIM + tid * 4] = o;
}

// ------------------------- launch -------------------------
extern "C" void kernel_launch(void* const* d_in, const int* in_sizes, int n_in,
                              void* d_out, int out_size)
{
    const float* text   = (const float*)d_in[0];
    const float* vision = (const float*)d_in[1];
    const float* ipw    = (const float*)d_in[2];
    const float* ipb    = (const float*)d_in[3];
    const float* outw   = (const float*)d_in[4];
    const float* outb   = (const float*)d_in[5];
    const float* lng    = (const float*)d_in[6];
    const float* lnb    = (const float*)d_in[7];

    float* out   = (float*)d_out;
    float* attnw = out + (size_t)MQ * DIM;

    float* attp;
    cudaGetSymbolAddress((void**)&attp, g_att);

    __half *tAhi, *tVhi, *tWhi, *tOhi, *Qhi, *Khi, *Vhi, *Chi;
    cudaGetSymbolAddress((void**)&tAhi, g_tAhi);
    cudaGetSymbolAddress((void**)&tVhi, g_tVhi);
    cudaGetSymbolAddress((void**)&tWhi, g_tWhi);
    cudaGetSymbolAddress((void**)&tOhi, g_tOhi);
    cudaGetSymbolAddress((void**)&Qhi, g_Qhi);
    cudaGetSymbolAddress((void**)&Khi, g_Khi);
    cudaGetSymbolAddress((void**)&Vhi, g_Vhi);
    cudaGetSymbolAddress((void**)&Chi, g_Chi);

    cudaFuncSetAttribute(attn_mma, cudaFuncAttributeMaxDynamicSharedMemorySize, ATTN_SMEM);
    cudaFuncSetAttribute(gemm_mma<0>, cudaFuncAttributeMaxDynamicSharedMemorySize, GSM_TOTAL);
    cudaFuncSetAttribute(gemm_mma<1>, cudaFuncAttributeMaxDynamicSharedMemorySize, GSM_TOTAL);
    cudaFuncSetAttribute(gemm_mma<2>, cudaFuncAttributeMaxDynamicSharedMemorySize, GSM_TOTAL);

    int n4;
    n4 = (MQ * DIM) / 4;
    cvt_hi<<<(n4 + 255) / 256, 256>>>((const float4*)text, (uint32_t*)tAhi, 1.0f, n4);
    n4 = (MK * DIM) / 4;
    cvt_hi<<<(n4 + 255) / 256, 256>>>((const float4*)vision, (uint32_t*)tVhi, 1.0f, n4);
    n4 = (3 * DIM * DIM) / 4;
    cvt_hi<<<(n4 + 255) / 256, 256>>>((const float4*)ipw, (uint32_t*)tWhi, WUP, n4);
    n4 = (DIM * DIM) / 4;
    cvt_hi<<<(n4 + 255) / 256, 256>>>((const float4*)outw, (uint32_t*)tOhi, WUP, n4);

    // Q (scaled fp16) = 0.125*(text @ Wq^T + bq)
    gemm_mma<1><<<dim3(DIM / 256, MQ / 128), 256, GSM_TOTAL>>>(
        tAhi, tWhi, ipb, nullptr, nullptr, Qhi, nullptr, MQ, DIM, DIM);
    // [K|V] fp16 = vision @ [Wk|Wv]^T + [bk|bv]
    gemm_mma<2><<<dim3(2 * DIM / 256, MK / 128), 256, GSM_TOTAL>>>(
        tVhi, tWhi + (size_t)DIM * DIM, ipb + DIM, nullptr, nullptr, Khi, Vhi, MK, 2 * DIM, DIM);
    // attention
    attn_mma<<<NB * (LQ / 32), 256, ATTN_SMEM>>>(attnw);
    // attended = ctx @ out_w^T + out_b + text
    gemm_mma<0><<<dim3(DIM / 256, MQ / 128), 256, GSM_TOTAL>>>(
        Chi, tOhi, outb, text, attp, nullptr, nullptr, MQ, DIM, DIM);
    // layernorm
    ln_kernel<<<MQ, 256>>>(attp, lng, lnb, out);
}

// round 10
// speedup vs baseline: 1.0311x; 1.0311x over previous
#include <cuda_runtime.h>
#include <cuda_fp16.h>
#include <cstdint>
#include <cstddef>

#define DIM 1024
#define NH 16
#define HD 64
#define NB 8
#define LQ 512
#define LKK 1024
#define MQ (NB*LQ)      // 4096
#define MK (NB*LKK)     // 8192
#define EPSV 1e-5f
#define QSCALE 0.125f
#define WUP 32.0f
#define WINV (1.0f/32.0f)

// ------------------------- scratch -------------------------
__device__ float g_att[(size_t)MQ * DIM];

__device__ __half g_tAhi[(size_t)MQ * DIM];          // text fp16
__device__ __half g_tVhi[(size_t)MK * DIM];          // vision fp16
__device__ __half g_tWhi[(size_t)3*DIM*DIM];         // 32*in_proj_w fp16
__device__ __half g_tOhi[(size_t)DIM*DIM];           // 32*out_w fp16
__device__ __half g_Qhi[(size_t)MQ * DIM];           // scaled Q
__device__ __half g_Khi[(size_t)MK * DIM];
__device__ __half g_Vhi[(size_t)MK * DIM];
__device__ __half g_Chi[(size_t)MQ * DIM];           // ctx

// ------------------------- helpers -------------------------
__device__ __forceinline__ uint32_t smem_to_u32(const void* p) {
    uint32_t a;
    asm("{ .reg .u64 t; cvta.to.shared.u64 t, %1; cvt.u32.u64 %0, t; }" : "=r"(a) : "l"(p));
    return a;
}
__device__ __forceinline__ void ldsm_x4(uint32_t* r, uint32_t addr) {
    asm volatile("ldmatrix.sync.aligned.m8n8.x4.shared.b16 {%0,%1,%2,%3}, [%4];"
        : "=r"(r[0]), "=r"(r[1]), "=r"(r[2]), "=r"(r[3]) : "r"(addr));
}
__device__ __forceinline__ void ldsm_x4_t(uint32_t* r, uint32_t addr) {
    asm volatile("ldmatrix.sync.aligned.m8n8.x4.trans.shared.b16 {%0,%1,%2,%3}, [%4];"
        : "=r"(r[0]), "=r"(r[1]), "=r"(r[2]), "=r"(r[3]) : "r"(addr));
}
__device__ __forceinline__ void mma16816(float* d, const uint32_t* a, const uint32_t* b) {
    asm volatile("mma.sync.aligned.m16n8k16.row.col.f32.f16.f16.f32 "
        "{%0,%1,%2,%3}, {%4,%5,%6,%7}, {%8,%9}, {%0,%1,%2,%3};"
        : "+f"(d[0]), "+f"(d[1]), "+f"(d[2]), "+f"(d[3])
        : "r"(a[0]), "r"(a[1]), "r"(a[2]), "r"(a[3]), "r"(b[0]), "r"(b[1]));
}
__device__ __forceinline__ uint32_t h2bits(float a, float b) {
    __half2 h = __floats2half2_rn(a, b);
    return *(uint32_t*)&h;
}
__device__ __forceinline__ void cp16(uint32_t saddr, const void* g) {
    asm volatile("cp.async.cg.shared.global [%0], [%1], 16;" :: "r"(saddr), "l"(g));
}
#define CP_COMMIT() asm volatile("cp.async.commit_group;" ::: "memory")
#define CP_WAIT0()  asm volatile("cp.async.wait_group 0;" ::: "memory")
#define CP_WAIT1()  asm volatile("cp.async.wait_group 1;" ::: "memory")

// ------------------------- conversion -------------------------
__global__ __launch_bounds__(256) void cvt_hi(const float4* __restrict__ x,
                                              uint32_t* __restrict__ hi,
                                              float scale, int n4)
{
    int i = blockIdx.x * blockDim.x + threadIdx.x;
    if (i >= n4) return;
    float4 v = x[i];
    hi[2 * i]     = h2bits(v.x * scale, v.y * scale);
    hi[2 * i + 1] = h2bits(v.z * scale, v.w * scale);
}

// ------------------------- mma.sync fp16 GEMM (128x128 tile, 3-stage) -------------------------
// C = A @ W^T (+bias/res). A fp16; W = 32*W fp16; acc * 1/32 in epilogue.
// KC=32; stage = A 8KB + W 8KB = 16KB; 3 stages = 48KB -> 2 CTAs/SM.
#define GT_TILE 8192
#define GSTAGE  (2 * GT_TILE)
#define GSM_TOTAL (3 * GSTAGE)

template<int MODE>
__global__ __launch_bounds__(256, 2) void gemm_mma(
    const __half* __restrict__ Ahi, const __half* __restrict__ Whi,
    const float* __restrict__ bias, const float* __restrict__ res,
    float* __restrict__ C,
    __half* __restrict__ h0, __half* __restrict__ h1,
    int M, int N, int K)
{
    extern __shared__ char sm[];
    const uint32_t sb = smem_to_u32(sm);

    const int tid  = threadIdx.x;
    const int wid  = tid >> 5;
    const int lane = tid & 31;
    const int bm = blockIdx.y * 128;
    const int bn = blockIdx.x * 128;
    const int m0 = (wid >> 2) * 64;
    const int n0 = (wid & 3) * 32;

    int lrow[2], lsl[2], loff[2];
#pragma unroll
    for (int i = 0; i < 2; i++) {
        int u = tid + i * 256;
        lrow[i] = u >> 2;
        lsl[i]  = u & 3;
        loff[i] = lrow[i] * 64 + ((lsl[i] << 4) ^ (((lrow[i] >> 1) & 3) << 4));
    }

    const int arow_l = lane & 15;
    const int a_hi   = lane >> 4;
    const int brow_l = (lane & 7) + ((lane & 16) ? 8 : 0);
    const int b_hi   = (lane & 8) ? 1 : 0;
    const int gid = lane >> 2, tig = lane & 3;

    float acc[4][4][4];
#pragma unroll
    for (int i = 0; i < 4; i++)
#pragma unroll
        for (int j = 0; j < 4; j++)
#pragma unroll
            for (int l = 0; l < 4; l++) acc[i][j][l] = 0.f;

    const int nch = K >> 5;

    // prologue: chunks 0,1 -> stages 0,1
#pragma unroll
    for (int c0 = 0; c0 < 2; c0++) {
        const uint32_t base = sb + c0 * GSTAGE;
        const int coff = c0 * 32;
#pragma unroll
        for (int i = 0; i < 2; i++) {
            cp16(base + loff[i],           Ahi + (size_t)(bm + lrow[i]) * K + coff + lsl[i] * 8);
            cp16(base + GT_TILE + loff[i], Whi + (size_t)(bn + lrow[i]) * K + coff + lsl[i] * 8);
        }
        CP_COMMIT();
    }

    int stg = 0;
    for (int c = 0; c < nch; c++) {
        if (c + 1 < nch) { CP_WAIT1(); } else { CP_WAIT0(); }
        __syncthreads();
        if (c + 2 < nch) {
            int ns = stg + 2; if (ns >= 3) ns -= 3;
            const uint32_t base = sb + ns * GSTAGE;
            const int coff = (c + 2) * 32;
#pragma unroll
            for (int i = 0; i < 2; i++) {
                cp16(base + loff[i],           Ahi + (size_t)(bm + lrow[i]) * K + coff + lsl[i] * 8);
                cp16(base + GT_TILE + loff[i], Whi + (size_t)(bn + lrow[i]) * K + coff + lsl[i] * 8);
            }
            CP_COMMIT();
        }
        const uint32_t tb = sb + stg * GSTAGE;
#pragma unroll
        for (int ks = 0; ks < 2; ks++) {
            uint32_t ah[4][4];
#pragma unroll
            for (int mf = 0; mf < 4; mf++) {
                const int row = m0 + mf * 16 + arow_l;
                const int sl  = ks * 2 + a_hi;
                ldsm_x4(ah[mf], tb + row * 64 + ((sl << 4) ^ (((row >> 1) & 3) << 4)));
            }
            uint32_t bh[2][4];
#pragma unroll
            for (int np = 0; np < 2; np++) {
                const int row = n0 + np * 16 + brow_l;
                const int sl  = ks * 2 + b_hi;
                ldsm_x4(bh[np], tb + GT_TILE + row * 64 + ((sl << 4) ^ (((row >> 1) & 3) << 4)));
            }
#pragma unroll
            for (int mf = 0; mf < 4; mf++)
#pragma unroll
                for (int np = 0; np < 2; np++)
#pragma unroll
                    for (int half = 0; half < 2; half++)
                        mma16816(acc[mf][np * 2 + half], ah[mf], &bh[np][half * 2]);
        }
        stg++; if (stg == 3) stg = 0;
    }

    // ---- epilogue ----
#pragma unroll
    for (int mf = 0; mf < 4; mf++) {
        const int mrow0 = bm + m0 + mf * 16 + gid;
#pragma unroll
        for (int nf = 0; nf < 4; nf++) {
            const int col = bn + n0 + nf * 8 + tig * 2;
            const float2 bia = *(const float2*)&bias[col];
            float* d = acc[mf][nf];
            float v00 = d[0] * WINV + bia.x, v01 = d[1] * WINV + bia.y;
            float v10 = d[2] * WINV + bia.x, v11 = d[3] * WINV + bia.y;
            if (MODE == 0) {
                const size_t i0 = (size_t)mrow0 * N + col;
                const size_t i1 = (size_t)(mrow0 + 8) * N + col;
                if (res) {
                    float2 r0 = *(const float2*)&res[i0];
                    float2 r1 = *(const float2*)&res[i1];
                    v00 += r0.x; v01 += r0.y; v10 += r1.x; v11 += r1.y;
                }
                *(float2*)&C[i0] = make_float2(v00, v01);
                *(float2*)&C[i1] = make_float2(v10, v11);
            } else if (MODE == 1) {
                v00 *= QSCALE; v01 *= QSCALE; v10 *= QSCALE; v11 *= QSCALE;
                const size_t i0 = (size_t)mrow0 * DIM + col;
                const size_t i1 = (size_t)(mrow0 + 8) * DIM + col;
                *(uint32_t*)&h0[i0] = h2bits(v00, v01);
                *(uint32_t*)&h0[i1] = h2bits(v10, v11);
            } else {
                __half* H = h0;
                int cc = col;
                if (col >= DIM) { H = h1; cc = col - DIM; }
                const size_t i0 = (size_t)mrow0 * DIM + cc;
                const size_t i1 = (size_t)(mrow0 + 8) * DIM + cc;
                *(uint32_t*)&H[i0] = h2bits(v00, v01);
                *(uint32_t*)&H[i1] = h2bits(v10, v11);
            }
        }
    }
}

// ------------------------- tensor-core attention (R8 config) -------------------------
#define SM_QH  131072
#define SM_KV0 135168
#define KV_BUF 16384
#define ATTN_SMEM (SM_KV0 + 2 * KV_BUF)   // 167936

__global__ __launch_bounds__(256) void attn_mma(float* __restrict__ attnw)
{
    extern __shared__ char sm[];
    float* S = (float*)sm;
    const uint32_t sb = smem_to_u32(sm);

    const int tid  = threadIdx.x;
    const int wid  = tid >> 5;
    const int lane = tid & 31;
    const int b  = blockIdx.x >> 4;
    const int q0 = (blockIdx.x & 15) << 5;

    const int ms  = (wid >> 2) * 16;
    const int ns  = (wid & 3) * 32;
    const int nv0 = (wid & 3) * 16;

    const int arow_l = lane & 15;
    const int axor   = (arow_l & 7) << 4;
    const int akb    = (lane >> 4) * 16;
    const int brow_l = (lane & 7) + ((lane & 16) ? 8 : 0);
    const int bxor   = (lane & 7) << 4;
    const int bkb    = (lane & 8) ? 16 : 0;
    const int gid = lane >> 2, tig = lane & 3;

    int krow[4], koff_s[4], kcu[4];
#pragma unroll
    for (int i = 0; i < 4; i++) {
        int u = tid + i * 256;
        krow[i] = u >> 3;
        kcu[i]  = u & 7;
        koff_s[i] = krow[i] * 128 + ((kcu[i] * 16) ^ ((krow[i] & 7) << 4));
    }
    const int qrow = tid >> 3, qcu = tid & 7;
    const int qoff = qrow * 128 + ((qcu * 16) ^ ((qrow & 7) << 4));

    const int vkey_l = ((lane >> 3) & 1) * 8 + (lane & 7);
    const int vdim   = nv0 + ((lane >> 4) ? 8 : 0);

    float awacc[4][32];
#pragma unroll
    for (int rr = 0; rr < 4; rr++)
#pragma unroll
        for (int j = 0; j < 32; j++) awacc[rr][j] = 0.f;

    for (int h = 0; h < NH; h++) {
        {
            size_t g = ((size_t)(b * LQ + q0 + qrow)) * DIM + h * HD + qcu * 8;
            *(uint4*)(sm + SM_QH + qoff) = *(const uint4*)(g_Qhi + g);
        }
        __syncthreads();

        // K chunk 0 -> buf 0
        {
#pragma unroll
            for (int i = 0; i < 4; i++) {
                size_t g = ((size_t)(b * LKK + krow[i])) * DIM + h * HD + kcu[i] * 8;
                cp16(sb + SM_KV0 + koff_s[i], g_Khi + g);
            }
            CP_COMMIT();
        }

        uint32_t qh[4][4];
#pragma unroll
        for (int ks = 0; ks < 4; ks++) {
            int koff = (ks * 32 + akb) ^ axor;
            ldsm_x4(qh[ks], sb + SM_QH + (ms + arow_l) * 128 + koff);
        }

        // ---- scores ----
        for (int kc = 0; kc < 8; kc++) {
            CP_WAIT0();
            __syncthreads();
            if (kc < 7) {
                const uint32_t base = sb + SM_KV0 + ((kc + 1) & 1) * KV_BUF;
#pragma unroll
                for (int i = 0; i < 4; i++) {
                    size_t g = ((size_t)(b * LKK + (kc + 1) * 128 + krow[i])) * DIM + h * HD + kcu[i] * 8;
                    cp16(base + koff_s[i], g_Khi + g);
                }
                CP_COMMIT();
            }
            const uint32_t kb = sb + SM_KV0 + (kc & 1) * KV_BUF;
            float acc[4][4];
#pragma unroll
            for (int i = 0; i < 4; i++)
#pragma unroll
                for (int j = 0; j < 4; j++) acc[i][j] = 0.f;
#pragma unroll
            for (int ks = 0; ks < 4; ks++) {
                const int bkoff = (ks * 32 + bkb) ^ bxor;
                uint32_t bh[2][4];
#pragma unroll
                for (int np = 0; np < 2; np++)
                    ldsm_x4(bh[np], kb + (ns + np * 16 + brow_l) * 128 + bkoff);
#pragma unroll
                for (int np = 0; np < 2; np++)
#pragma unroll
                    for (int half = 0; half < 2; half++)
                        mma16816(acc[np * 2 + half], qh[ks], &bh[np][half * 2]);
            }
#pragma unroll
            for (int nf = 0; nf < 4; nf++) {
                const int col = kc * 128 + ns + nf * 8 + tig * 2;
                *(float2*)&S[(ms + gid) * LKK + col]     = make_float2(acc[nf][0], acc[nf][1]);
                *(float2*)&S[(ms + gid + 8) * LKK + col] = make_float2(acc[nf][2], acc[nf][3]);
            }
        }
        __syncthreads();

        // V chunk 0 -> buf 0 (overlaps softmax)
        {
#pragma unroll
            for (int i = 0; i < 4; i++) {
                size_t g = ((size_t)(b * LKK + krow[i])) * DIM + h * HD + kcu[i] * 8;
                cp16(sb + SM_KV0 + koff_s[i], g_Vhi + g);
            }
            CP_COMMIT();
        }

        // ---- fused softmax + register attnw + fp16 P ----
#pragma unroll
        for (int rr = 0; rr < 4; rr++) {
            const int r = wid * 4 + rr;
            float v[32];
            const float* src = &S[r * LKK + lane * 32];
#pragma unroll
            for (int j = 0; j < 8; j++) *(float4*)&v[j * 4] = *(const float4*)&src[j * 4];
            float mx = -1e30f;
#pragma unroll
            for (int j = 0; j < 32; j++) mx = fmaxf(mx, v[j]);
#pragma unroll
            for (int o = 16; o > 0; o >>= 1) mx = fmaxf(mx, __shfl_xor_sync(0xffffffffu, mx, o));
            float s = 0.f;
#pragma unroll
            for (int j = 0; j < 32; j++) { v[j] = __expf(v[j] - mx); s += v[j]; }
#pragma unroll
            for (int o = 16; o > 0; o >>= 1) s += __shfl_xor_sync(0xffffffffu, s, o);
            const float inv = 1.0f / s;
#pragma unroll
            for (int j = 0; j < 32; j++) v[j] *= inv;

#pragma unroll
            for (int j = 0; j < 32; j++) awacc[rr][j] += v[j];

            char* rb = sm + r * 4096;
            const int sw = (r & 7) << 4;
#pragma unroll
            for (int j = 0; j < 4; j++) {
                uint32_t h4[4];
#pragma unroll
                for (int p = 0; p < 4; p++)
                    h4[p] = h2bits(v[j * 8 + p * 2], v[j * 8 + p * 2 + 1]);
                const int off = ((lane * 4 + j) * 16) ^ sw;
                *(uint4*)(rb + off) = *(uint4*)h4;
            }
        }

        // ---- ctx = P @ V ----
        float cacc[2][4];
#pragma unroll
        for (int g = 0; g < 2; g++)
#pragma unroll
            for (int l = 0; l < 4; l++) cacc[g][l] = 0.f;

        for (int kc = 0; kc < 8; kc++) {
            CP_WAIT0();
            __syncthreads();
            if (kc < 7) {
                const uint32_t base = sb + SM_KV0 + ((kc + 1) & 1) * KV_BUF;
#pragma unroll
                for (int i = 0; i < 4; i++) {
                    size_t g = ((size_t)(b * LKK + (kc + 1) * 128 + krow[i])) * DIM + h * HD + kcu[i] * 8;
                    cp16(base + koff_s[i], g_Vhi + g);
                }
                CP_COMMIT();
            }
            const uint32_t vb = sb + SM_KV0 + (kc & 1) * KV_BUF;
            const int mrow = ms + arow_l;
            const uint32_t pbase = sb + mrow * 4096;
            const int psw = (mrow & 7) << 4;
#pragma unroll
            for (int ks = 0; ks < 8; ks++) {
                const int poff = ((kc * 256 + ks * 32 + akb) ^ psw);
                uint32_t pah[4];
                ldsm_x4(pah, pbase + poff);
                const int key = ks * 16 + vkey_l;
                const uint32_t vaddr = vb + key * 128 + ((vdim * 2) ^ ((key & 7) << 4));
                uint32_t vh[4];
                ldsm_x4_t(vh, vaddr);
#pragma unroll
                for (int g = 0; g < 2; g++)
                    mma16816(cacc[g], pah, &vh[g * 2]);
            }
        }
#pragma unroll
        for (int g = 0; g < 2; g++) {
            const int col = h * HD + nv0 + g * 8 + tig * 2;
            const size_t i0 = ((size_t)(b * LQ + q0 + ms + gid)) * DIM + col;
            const size_t i1 = ((size_t)(b * LQ + q0 + ms + gid + 8)) * DIM + col;
            *(uint32_t*)&g_Chi[i0] = h2bits(cacc[g][0], cacc[g][1]);
            *(uint32_t*)&g_Chi[i1] = h2bits(cacc[g][2], cacc[g][3]);
        }
    }

    // ---- final attn_weights write (mean over heads) ----
    {
        const float invh = 1.0f / NH;
#pragma unroll
        for (int rr = 0; rr < 4; rr++) {
            float* aw = attnw + ((size_t)(b * LQ + q0 + wid * 4 + rr)) * LKK + lane * 32;
#pragma unroll
            for (int j = 0; j < 8; j++) {
                float4 p = make_float4(awacc[rr][j*4] * invh,   awacc[rr][j*4+1] * invh,
                                       awacc[rr][j*4+2] * invh, awacc[rr][j*4+3] * invh);
                *(float4*)&aw[j * 4] = p;
            }
        }
    }
}

// ------------------------- layernorm -------------------------
__global__ __launch_bounds__(256) void ln_kernel(
    const float* __restrict__ X, const float* __restrict__ gam,
    const float* __restrict__ bet, float* __restrict__ out)
{
    __shared__ float red[64];
    __shared__ float s_mu, s_rinv;
    const int r = blockIdx.x, tid = threadIdx.x;
    const float* x = X + (size_t)r * DIM;
    float4 v = *(const float4*)&x[tid * 4];
    float s  = v.x + v.y + v.z + v.w;
    float sq = v.x * v.x + v.y * v.y + v.z * v.z + v.w * v.w;
#pragma unroll
    for (int o = 16; o > 0; o >>= 1) {
        s  += __shfl_xor_sync(0xffffffffu, s, o);
        sq += __shfl_xor_sync(0xffffffffu, sq, o);
    }
    const int w = tid >> 5;
    if ((tid & 31) == 0) { red[w] = s; red[32 + w] = sq; }
    __syncthreads();
    if (tid == 0) {
        float S = 0, Q = 0;
        for (int i = 0; i < 8; i++) { S += red[i]; Q += red[32 + i]; }
        float mu = S * (1.0f / DIM);
        float var = Q * (1.0f / DIM) - mu * mu;
        s_mu = mu;
        s_rinv = rsqrtf(var + EPSV);
    }
    __syncthreads();
    const float mu = s_mu, rinv = s_rinv;
    float4 gg = *(const float4*)&gam[tid * 4];
    float4 bb = *(const float4*)&bet[tid * 4];
    float4 o;
    o.x = (v.x - mu) * rinv * gg.x + bb.x;
    o.y = (v.y - mu) * rinv * gg.y + bb.y;
    o.z = (v.z - mu) * rinv * gg.z + bb.z;
    o.w = (v.w - mu) * rinv * gg.w + bb.w;
    *(float4*)&out[(size_t)r * DIM + tid * 4] = o;
}

// ------------------------- launch -------------------------
extern "C" void kernel_launch(void* const* d_in, const int* in_sizes, int n_in,
                              void* d_out, int out_size)
{
    const float* text   = (const float*)d_in[0];
    const float* vision = (const float*)d_in[1];
    const float* ipw    = (const float*)d_in[2];
    const float* ipb    = (const float*)d_in[3];
    const float* outw   = (const float*)d_in[4];
    const float* outb   = (const float*)d_in[5];
    const float* lng    = (const float*)d_in[6];
    const float* lnb    = (const float*)d_in[7];

    float* out   = (float*)d_out;
    float* attnw = out + (size_t)MQ * DIM;

    float* attp;
    cudaGetSymbolAddress((void**)&attp, g_att);

    __half *tAhi, *tVhi, *tWhi, *tOhi, *Qhi, *Khi, *Vhi, *Chi;
    cudaGetSymbolAddress((void**)&tAhi, g_tAhi);
    cudaGetSymbolAddress((void**)&tVhi, g_tVhi);
    cudaGetSymbolAddress((void**)&tWhi, g_tWhi);
    cudaGetSymbolAddress((void**)&tOhi, g_tOhi);
    cudaGetSymbolAddress((void**)&Qhi, g_Qhi);
    cudaGetSymbolAddress((void**)&Khi, g_Khi);
    cudaGetSymbolAddress((void**)&Vhi, g_Vhi);
    cudaGetSymbolAddress((void**)&Chi, g_Chi);

    cudaFuncSetAttribute(attn_mma, cudaFuncAttributeMaxDynamicSharedMemorySize, ATTN_SMEM);
    cudaFuncSetAttribute(gemm_mma<0>, cudaFuncAttributeMaxDynamicSharedMemorySize, GSM_TOTAL);
    cudaFuncSetAttribute(gemm_mma<1>, cudaFuncAttributeMaxDynamicSharedMemorySize, GSM_TOTAL);
    cudaFuncSetAttribute(gemm_mma<2>, cudaFuncAttributeMaxDynamicSharedMemorySize, GSM_TOTAL);

    int n4;
    n4 = (MQ * DIM) / 4;
    cvt_hi<<<(n4 + 255) / 256, 256>>>((const float4*)text, (uint32_t*)tAhi, 1.0f, n4);
    n4 = (MK * DIM) / 4;
    cvt_hi<<<(n4 + 255) / 256, 256>>>((const float4*)vision, (uint32_t*)tVhi, 1.0f, n4);
    n4 = (3 * DIM * DIM) / 4;
    cvt_hi<<<(n4 + 255) / 256, 256>>>((const float4*)ipw, (uint32_t*)tWhi, WUP, n4);
    n4 = (DIM * DIM) / 4;
    cvt_hi<<<(n4 + 255) / 256, 256>>>((const float4*)outw, (uint32_t*)tOhi, WUP, n4);

    // Q (scaled fp16) = 0.125*(text @ Wq^T + bq)
    gemm_mma<1><<<dim3(DIM / 128, MQ / 128), 256, GSM_TOTAL>>>(
        tAhi, tWhi, ipb, nullptr, nullptr, Qhi, nullptr, MQ, DIM, DIM);
    // [K|V] fp16 = vision @ [Wk|Wv]^T + [bk|bv]
    gemm_mma<2><<<dim3(2 * DIM / 128, MK / 128), 256, GSM_TOTAL>>>(
        tVhi, tWhi + (size_t)DIM * DIM, ipb + DIM, nullptr, nullptr, Khi, Vhi, MK, 2 * DIM, DIM);
    // attention
    attn_mma<<<NB * (LQ / 32), 256, ATTN_SMEM>>>(attnw);
    // attended = ctx @ out_w^T + out_b + text
    gemm_mma<0><<<dim3(DIM / 128, MQ / 128), 256, GSM_TOTAL>>>(
        Chi, tOhi, outb, text, attp, nullptr, nullptr, MQ, DIM, DIM);
    // layernorm
    ln_kernel<<<MQ, 256>>>(attp, lng, lnb, out);
}

// round 11
// speedup vs baseline: 1.1588x; 1.1238x over previous
#include <cuda_runtime.h>
#include <cuda_fp16.h>
#include <cstdint>
#include <cstddef>

#define DIM 1024
#define NH 16
#define HD 64
#define NB 8
#define LQ 512
#define LKK 1024
#define MQ (NB*LQ)      // 4096
#define MK (NB*LKK)     // 8192
#define EPSV 1e-5f
#define QSCALE 0.125f
#define WUP 32.0f
#define WINV (1.0f/32.0f)

// ------------------------- scratch -------------------------
__device__ float g_att[(size_t)MQ * DIM];

__device__ __half g_tAhi[(size_t)MQ * DIM];          // text fp16
__device__ __half g_tVhi[(size_t)MK * DIM];          // vision fp16
__device__ __half g_tWhi[(size_t)3*DIM*DIM];         // 32*in_proj_w fp16
__device__ __half g_tOhi[(size_t)DIM*DIM];           // 32*out_w fp16
__device__ __half g_Qhi[(size_t)MQ * DIM];           // scaled Q
__device__ __half g_Khi[(size_t)MK * DIM];
__device__ __half g_Vhi[(size_t)MK * DIM];
__device__ __half g_Chi[(size_t)MQ * DIM];           // ctx

// ------------------------- helpers -------------------------
__device__ __forceinline__ uint32_t smem_to_u32(const void* p) {
    uint32_t a;
    asm("{ .reg .u64 t; cvta.to.shared.u64 t, %1; cvt.u32.u64 %0, t; }" : "=r"(a) : "l"(p));
    return a;
}
__device__ __forceinline__ void ldsm_x4(uint32_t* r, uint32_t addr) {
    asm volatile("ldmatrix.sync.aligned.m8n8.x4.shared.b16 {%0,%1,%2,%3}, [%4];"
        : "=r"(r[0]), "=r"(r[1]), "=r"(r[2]), "=r"(r[3]) : "r"(addr));
}
__device__ __forceinline__ void ldsm_x4_t(uint32_t* r, uint32_t addr) {
    asm volatile("ldmatrix.sync.aligned.m8n8.x4.trans.shared.b16 {%0,%1,%2,%3}, [%4];"
        : "=r"(r[0]), "=r"(r[1]), "=r"(r[2]), "=r"(r[3]) : "r"(addr));
}
__device__ __forceinline__ void mma16816(float* d, const uint32_t* a, const uint32_t* b) {
    asm volatile("mma.sync.aligned.m16n8k16.row.col.f32.f16.f16.f32 "
        "{%0,%1,%2,%3}, {%4,%5,%6,%7}, {%8,%9}, {%0,%1,%2,%3};"
        : "+f"(d[0]), "+f"(d[1]), "+f"(d[2]), "+f"(d[3])
        : "r"(a[0]), "r"(a[1]), "r"(a[2]), "r"(a[3]), "r"(b[0]), "r"(b[1]));
}
__device__ __forceinline__ uint32_t h2bits(float a, float b) {
    __half2 h = __floats2half2_rn(a, b);
    return *(uint32_t*)&h;
}
__device__ __forceinline__ void cp16(uint32_t saddr, const void* g) {
    asm volatile("cp.async.cg.shared.global [%0], [%1], 16;" :: "r"(saddr), "l"(g));
}
#define CP_COMMIT() asm volatile("cp.async.commit_group;" ::: "memory")
#define CP_WAIT0()  asm volatile("cp.async.wait_group 0;" ::: "memory")

// ------------------------- conversion -------------------------
__global__ __launch_bounds__(256) void cvt_hi(const float4* __restrict__ x,
                                              uint32_t* __restrict__ hi,
                                              float scale, int n4)
{
    int i = blockIdx.x * blockDim.x + threadIdx.x;
    if (i >= n4) return;
    float4 v = x[i];
    hi[2 * i]     = h2bits(v.x * scale, v.y * scale);
    hi[2 * i + 1] = h2bits(v.z * scale, v.w * scale);
}

// ------------------------- mma.sync fp16 GEMM (R8 config: depth-2) -------------------------
#define GT_TILE 8192
#define GSM_TOTAL (4 * GT_TILE)

template<int MODE>
__global__ __launch_bounds__(256, 2) void gemm_mma(
    const __half* __restrict__ Ahi, const __half* __restrict__ Whi,
    const float* __restrict__ bias, const float* __restrict__ res,
    float* __restrict__ C,
    __half* __restrict__ h0, __half* __restrict__ h1,
    int M, int N, int K)
{
    extern __shared__ char sm[];
    const uint32_t sb = smem_to_u32(sm);

    const int tid  = threadIdx.x;
    const int wid  = tid >> 5;
    const int lane = tid & 31;
    const int bm = blockIdx.y * 128;
    const int bn = blockIdx.x * 128;
    const int m0 = (wid >> 2) * 64;
    const int n0 = (wid & 3) * 32;

    int lrow[2], lsl[2], loff[2];
#pragma unroll
    for (int i = 0; i < 2; i++) {
        int u = tid + i * 256;
        lrow[i] = u >> 2;
        lsl[i]  = u & 3;
        loff[i] = lrow[i] * 64 + ((lsl[i] << 4) ^ (((lrow[i] >> 1) & 3) << 4));
    }

    const int arow_l = lane & 15;
    const int a_hi   = lane >> 4;
    const int brow_l = (lane & 7) + ((lane & 16) ? 8 : 0);
    const int b_hi   = (lane & 8) ? 1 : 0;
    const int gid = lane >> 2, tig = lane & 3;

    float acc[4][4][4];
#pragma unroll
    for (int i = 0; i < 4; i++)
#pragma unroll
        for (int j = 0; j < 4; j++)
#pragma unroll
            for (int l = 0; l < 4; l++) acc[i][j][l] = 0.f;

    const int nch = K >> 5;

    {
#pragma unroll
        for (int i = 0; i < 2; i++) {
            const int col = lsl[i] * 8;
            cp16(sb + loff[i],           Ahi + (size_t)(bm + lrow[i]) * K + col);
            cp16(sb + GT_TILE + loff[i], Whi + (size_t)(bn + lrow[i]) * K + col);
        }
        CP_COMMIT();
    }

    for (int c = 0; c < nch; c++) {
        CP_WAIT0();
        __syncthreads();
        if (c + 1 < nch) {
            const uint32_t base = sb + ((c + 1) & 1) * 2 * GT_TILE;
            const int coff = (c + 1) * 32;
#pragma unroll
            for (int i = 0; i < 2; i++) {
                const int col = coff + lsl[i] * 8;
                cp16(base + loff[i],           Ahi + (size_t)(bm + lrow[i]) * K + col);
                cp16(base + GT_TILE + loff[i], Whi + (size_t)(bn + lrow[i]) * K + col);
            }
            CP_COMMIT();
        }
        const uint32_t tb = sb + (c & 1) * 2 * GT_TILE;
#pragma unroll
        for (int ks = 0; ks < 2; ks++) {
            uint32_t ah[4][4];
#pragma unroll
            for (int mf = 0; mf < 4; mf++) {
                const int row = m0 + mf * 16 + arow_l;
                const int sl  = ks * 2 + a_hi;
                ldsm_x4(ah[mf], tb + row * 64 + ((sl << 4) ^ (((row >> 1) & 3) << 4)));
            }
            uint32_t bh[2][4];
#pragma unroll
            for (int np = 0; np < 2; np++) {
                const int row = n0 + np * 16 + brow_l;
                const int sl  = ks * 2 + b_hi;
                ldsm_x4(bh[np], tb + GT_TILE + row * 64 + ((sl << 4) ^ (((row >> 1) & 3) << 4)));
            }
#pragma unroll
            for (int mf = 0; mf < 4; mf++)
#pragma unroll
                for (int np = 0; np < 2; np++)
#pragma unroll
                    for (int half = 0; half < 2; half++)
                        mma16816(acc[mf][np * 2 + half], ah[mf], &bh[np][half * 2]);
        }
    }

    // ---- epilogue ----
#pragma unroll
    for (int mf = 0; mf < 4; mf++) {
        const int mrow0 = bm + m0 + mf * 16 + gid;
#pragma unroll
        for (int nf = 0; nf < 4; nf++) {
            const int col = bn + n0 + nf * 8 + tig * 2;
            const float2 bia = *(const float2*)&bias[col];
            float* d = acc[mf][nf];
            float v00 = d[0] * WINV + bia.x, v01 = d[1] * WINV + bia.y;
            float v10 = d[2] * WINV + bia.x, v11 = d[3] * WINV + bia.y;
            if (MODE == 0) {
                const size_t i0 = (size_t)mrow0 * N + col;
                const size_t i1 = (size_t)(mrow0 + 8) * N + col;
                if (res) {
                    float2 r0 = *(const float2*)&res[i0];
                    float2 r1 = *(const float2*)&res[i1];
                    v00 += r0.x; v01 += r0.y; v10 += r1.x; v11 += r1.y;
                }
                *(float2*)&C[i0] = make_float2(v00, v01);
                *(float2*)&C[i1] = make_float2(v10, v11);
            } else if (MODE == 1) {
                v00 *= QSCALE; v01 *= QSCALE; v10 *= QSCALE; v11 *= QSCALE;
                const size_t i0 = (size_t)mrow0 * DIM + col;
                const size_t i1 = (size_t)(mrow0 + 8) * DIM + col;
                *(uint32_t*)&h0[i0] = h2bits(v00, v01);
                *(uint32_t*)&h0[i1] = h2bits(v10, v11);
            } else {
                __half* H = h0;
                int cc = col;
                if (col >= DIM) { H = h1; cc = col - DIM; }
                const size_t i0 = (size_t)mrow0 * DIM + cc;
                const size_t i1 = (size_t)(mrow0 + 8) * DIM + cc;
                *(uint32_t*)&H[i0] = h2bits(v00, v01);
                *(uint32_t*)&H[i1] = h2bits(v10, v11);
            }
        }
    }
}

// ------------------------- tensor-core attention (bank-conflict-free S) -------------------------
// S: 32 rows x 1028 floats (4112B stride, padding rotates banks per row).
// P overlays first 2048B of each S row (fp16, 16B-slot XOR swizzle).
#define SSTR   1028
#define SROW_B 4112
#define SM_QH  131584           // 32*4112
#define SM_KV0 135680
#define KV_BUF 16384
#define ATTN_SMEM (SM_KV0 + 2 * KV_BUF)   // 168448

__global__ __launch_bounds__(256) void attn_mma(float* __restrict__ attnw)
{
    extern __shared__ char sm[];
    float* S = (float*)sm;
    const uint32_t sb = smem_to_u32(sm);

    const int tid  = threadIdx.x;
    const int wid  = tid >> 5;
    const int lane = tid & 31;
    const int b  = blockIdx.x >> 4;
    const int q0 = (blockIdx.x & 15) << 5;

    const int ms  = (wid >> 2) * 16;
    const int ns  = (wid & 3) * 32;
    const int nv0 = (wid & 3) * 16;

    const int arow_l = lane & 15;
    const int axor   = (arow_l & 7) << 4;
    const int akb    = (lane >> 4) * 16;
    const int brow_l = (lane & 7) + ((lane & 16) ? 8 : 0);
    const int bxor   = (lane & 7) << 4;
    const int bkb    = (lane & 8) ? 16 : 0;
    const int gid = lane >> 2, tig = lane & 3;

    int krow[4], koff_s[4], kcu[4];
#pragma unroll
    for (int i = 0; i < 4; i++) {
        int u = tid + i * 256;
        krow[i] = u >> 3;
        kcu[i]  = u & 7;
        koff_s[i] = krow[i] * 128 + ((kcu[i] * 16) ^ ((krow[i] & 7) << 4));
    }
    const int qrow = tid >> 3, qcu = tid & 7;
    const int qoff = qrow * 128 + ((qcu * 16) ^ ((qrow & 7) << 4));

    const int vkey_l = ((lane >> 3) & 1) * 8 + (lane & 7);
    const int vdim   = nv0 + ((lane >> 4) ? 8 : 0);

    // attnw accumulator: rows wid*4+rr, cols j*128 + lane*4 + {0..3}
    float awacc[4][32];
#pragma unroll
    for (int rr = 0; rr < 4; rr++)
#pragma unroll
        for (int j = 0; j < 32; j++) awacc[rr][j] = 0.f;

    for (int h = 0; h < NH; h++) {
        {
            size_t g = ((size_t)(b * LQ + q0 + qrow)) * DIM + h * HD + qcu * 8;
            *(uint4*)(sm + SM_QH + qoff) = *(const uint4*)(g_Qhi + g);
        }
        __syncthreads();

        // K chunk 0 -> buf 0
        {
#pragma unroll
            for (int i = 0; i < 4; i++) {
                size_t g = ((size_t)(b * LKK + krow[i])) * DIM + h * HD + kcu[i] * 8;
                cp16(sb + SM_KV0 + koff_s[i], g_Khi + g);
            }
            CP_COMMIT();
        }

        uint32_t qh[4][4];
#pragma unroll
        for (int ks = 0; ks < 4; ks++) {
            int koff = (ks * 32 + akb) ^ axor;
            ldsm_x4(qh[ks], sb + SM_QH + (ms + arow_l) * 128 + koff);
        }

        // ---- scores ----
        for (int kc = 0; kc < 8; kc++) {
            CP_WAIT0();
            __syncthreads();
            if (kc < 7) {
                const uint32_t base = sb + SM_KV0 + ((kc + 1) & 1) * KV_BUF;
#pragma unroll
                for (int i = 0; i < 4; i++) {
                    size_t g = ((size_t)(b * LKK + (kc + 1) * 128 + krow[i])) * DIM + h * HD + kcu[i] * 8;
                    cp16(base + koff_s[i], g_Khi + g);
                }
                CP_COMMIT();
            }
            const uint32_t kb = sb + SM_KV0 + (kc & 1) * KV_BUF;
            float acc[4][4];
#pragma unroll
            for (int i = 0; i < 4; i++)
#pragma unroll
                for (int j = 0; j < 4; j++) acc[i][j] = 0.f;
#pragma unroll
            for (int ks = 0; ks < 4; ks++) {
                const int bkoff = (ks * 32 + bkb) ^ bxor;
                uint32_t bh[2][4];
#pragma unroll
                for (int np = 0; np < 2; np++)
                    ldsm_x4(bh[np], kb + (ns + np * 16 + brow_l) * 128 + bkoff);
#pragma unroll
                for (int np = 0; np < 2; np++)
#pragma unroll
                    for (int half = 0; half < 2; half++)
                        mma16816(acc[np * 2 + half], qh[ks], &bh[np][half * 2]);
            }
#pragma unroll
            for (int nf = 0; nf < 4; nf++) {
                const int col = kc * 128 + ns + nf * 8 + tig * 2;
                *(float2*)&S[(ms + gid) * SSTR + col]     = make_float2(acc[nf][0], acc[nf][1]);
                *(float2*)&S[(ms + gid + 8) * SSTR + col] = make_float2(acc[nf][2], acc[nf][3]);
            }
        }
        __syncthreads();

        // V chunk 0 -> buf 0 (overlaps softmax)
        {
#pragma unroll
            for (int i = 0; i < 4; i++) {
                size_t g = ((size_t)(b * LKK + krow[i])) * DIM + h * HD + kcu[i] * 8;
                cp16(sb + SM_KV0 + koff_s[i], g_Vhi + g);
            }
            CP_COMMIT();
        }

        // ---- fused softmax + register attnw + fp16 P (conflict-free lane mapping) ----
#pragma unroll
        for (int rr = 0; rr < 4; rr++) {
            const int r = wid * 4 + rr;
            float v[32];
            const float* src = &S[r * SSTR + lane * 4];
#pragma unroll
            for (int j = 0; j < 8; j++) *(float4*)&v[j * 4] = *(const float4*)&src[j * 128];
            float mx = -1e30f;
#pragma unroll
            for (int j = 0; j < 32; j++) mx = fmaxf(mx, v[j]);
#pragma unroll
            for (int o = 16; o > 0; o >>= 1) mx = fmaxf(mx, __shfl_xor_sync(0xffffffffu, mx, o));
            float s = 0.f;
#pragma unroll
            for (int j = 0; j < 32; j++) { v[j] = __expf(v[j] - mx); s += v[j]; }
#pragma unroll
            for (int o = 16; o > 0; o >>= 1) s += __shfl_xor_sync(0xffffffffu, s, o);
            const float inv = 1.0f / s;
#pragma unroll
            for (int j = 0; j < 32; j++) v[j] *= inv;

#pragma unroll
            for (int j = 0; j < 32; j++) awacc[rr][j] += v[j];

            // P fp16: cols j*128 + lane*4 .. +3  ->  swizzled 16B-slot layout
            char* rb = sm + r * SROW_B;
            const int sw = (r & 7) << 4;
            const int half8 = (lane & 1) << 3;
            const int slot16 = (lane >> 1) << 4;
#pragma unroll
            for (int j = 0; j < 8; j++) {
                uint2 p;
                p.x = h2bits(v[j * 4],     v[j * 4 + 1]);
                p.y = h2bits(v[j * 4 + 2], v[j * 4 + 3]);
                const int off = ((j * 256 + slot16) ^ sw) + half8;
                *(uint2*)(rb + off) = p;
            }
        }

        // ---- ctx = P @ V ----
        float cacc[2][4];
#pragma unroll
        for (int g = 0; g < 2; g++)
#pragma unroll
            for (int l = 0; l < 4; l++) cacc[g][l] = 0.f;

        for (int kc = 0; kc < 8; kc++) {
            CP_WAIT0();
            __syncthreads();
            if (kc < 7) {
                const uint32_t base = sb + SM_KV0 + ((kc + 1) & 1) * KV_BUF;
#pragma unroll
                for (int i = 0; i < 4; i++) {
                    size_t g = ((size_t)(b * LKK + (kc + 1) * 128 + krow[i])) * DIM + h * HD + kcu[i] * 8;
                    cp16(base + koff_s[i], g_Vhi + g);
                }
                CP_COMMIT();
            }
            const uint32_t vb = sb + SM_KV0 + (kc & 1) * KV_BUF;
            const int mrow = ms + arow_l;
            const uint32_t pbase = sb + mrow * SROW_B;
            const int psw = (mrow & 7) << 4;
#pragma unroll
            for (int ks = 0; ks < 8; ks++) {
                const int poff = ((kc * 256 + ks * 32 + akb) ^ psw);
                uint32_t pah[4];
                ldsm_x4(pah, pbase + poff);
                const int key = ks * 16 + vkey_l;
                const uint32_t vaddr = vb + key * 128 + ((vdim * 2) ^ ((key & 7) << 4));
                uint32_t vh[4];
                ldsm_x4_t(vh, vaddr);
#pragma unroll
                for (int g = 0; g < 2; g++)
                    mma16816(cacc[g], pah, &vh[g * 2]);
            }
        }
#pragma unroll
        for (int g = 0; g < 2; g++) {
            const int col = h * HD + nv0 + g * 8 + tig * 2;
            const size_t i0 = ((size_t)(b * LQ + q0 + ms + gid)) * DIM + col;
            const size_t i1 = ((size_t)(b * LQ + q0 + ms + gid + 8)) * DIM + col;
            *(uint32_t*)&g_Chi[i0] = h2bits(cacc[g][0], cacc[g][1]);
            *(uint32_t*)&g_Chi[i1] = h2bits(cacc[g][2], cacc[g][3]);
        }
    }

    // ---- final attn_weights write (mean over heads) ----
    {
        const float invh = 1.0f / NH;
#pragma unroll
        for (int rr = 0; rr < 4; rr++) {
            float* aw = attnw + ((size_t)(b * LQ + q0 + wid * 4 + rr)) * LKK + lane * 4;
#pragma unroll
            for (int j = 0; j < 8; j++) {
                float4 p = make_float4(awacc[rr][j*4] * invh,   awacc[rr][j*4+1] * invh,
                                       awacc[rr][j*4+2] * invh, awacc[rr][j*4+3] * invh);
                *(float4*)&aw[j * 128] = p;
            }
        }
    }
}

// ------------------------- layernorm -------------------------
__global__ __launch_bounds__(256) void ln_kernel(
    const float* __restrict__ X, const float* __restrict__ gam,
    const float* __restrict__ bet, float* __restrict__ out)
{
    __shared__ float red[64];
    __shared__ float s_mu, s_rinv;
    const int r = blockIdx.x, tid = threadIdx.x;
    const float* x = X + (size_t)r * DIM;
    float4 v = *(const float4*)&x[tid * 4];
    float s  = v.x + v.y + v.z + v.w;
    float sq = v.x * v.x + v.y * v.y + v.z * v.z + v.w * v.w;
#pragma unroll
    for (int o = 16; o > 0; o >>= 1) {
        s  += __shfl_xor_sync(0xffffffffu, s, o);
        sq += __shfl_xor_sync(0xffffffffu, sq, o);
    }
    const int w = tid >> 5;
    if ((tid & 31) == 0) { red[w] = s; red[32 + w] = sq; }
    __syncthreads();
    if (tid == 0) {
        float S = 0, Q = 0;
        for (int i = 0; i < 8; i++) { S += red[i]; Q += red[32 + i]; }
        float mu = S * (1.0f / DIM);
        float var = Q * (1.0f / DIM) - mu * mu;
        s_mu = mu;
        s_rinv = rsqrtf(var + EPSV);
    }
    __syncthreads();
    const float mu = s_mu, rinv = s_rinv;
    float4 gg = *(const float4*)&gam[tid * 4];
    float4 bb = *(const float4*)&bet[tid * 4];
    float4 o;
    o.x = (v.x - mu) * rinv * gg.x + bb.x;
    o.y = (v.y - mu) * rinv * gg.y + bb.y;
    o.z = (v.z - mu) * rinv * gg.z + bb.z;
    o.w = (v.w - mu) * rinv * gg.w + bb.w;
    *(float4*)&out[(size_t)r * DIM + tid * 4] = o;
}

// ------------------------- launch -------------------------
extern "C" void kernel_launch(void* const* d_in, const int* in_sizes, int n_in,
                              void* d_out, int out_size)
{
    const float* text   = (const float*)d_in[0];
    const float* vision = (const float*)d_in[1];
    const float* ipw    = (const float*)d_in[2];
    const float* ipb    = (const float*)d_in[3];
    const float* outw   = (const float*)d_in[4];
    const float* outb   = (const float*)d_in[5];
    const float* lng    = (const float*)d_in[6];
    const float* lnb    = (const float*)d_in[7];

    float* out   = (float*)d_out;
    float* attnw = out + (size_t)MQ * DIM;

    float* attp;
    cudaGetSymbolAddress((void**)&attp, g_att);

    __half *tAhi, *tVhi, *tWhi, *tOhi, *Qhi, *Khi, *Vhi, *Chi;
    cudaGetSymbolAddress((void**)&tAhi, g_tAhi);
    cudaGetSymbolAddress((void**)&tVhi, g_tVhi);
    cudaGetSymbolAddress((void**)&tWhi, g_tWhi);
    cudaGetSymbolAddress((void**)&tOhi, g_tOhi);
    cudaGetSymbolAddress((void**)&Qhi, g_Qhi);
    cudaGetSymbolAddress((void**)&Khi, g_Khi);
    cudaGetSymbolAddress((void**)&Vhi, g_Vhi);
    cudaGetSymbolAddress((void**)&Chi, g_Chi);

    cudaFuncSetAttribute(attn_mma, cudaFuncAttributeMaxDynamicSharedMemorySize, ATTN_SMEM);
    cudaFuncSetAttribute(gemm_mma<0>, cudaFuncAttributeMaxDynamicSharedMemorySize, GSM_TOTAL);
    cudaFuncSetAttribute(gemm_mma<1>, cudaFuncAttributeMaxDynamicSharedMemorySize, GSM_TOTAL);
    cudaFuncSetAttribute(gemm_mma<2>, cudaFuncAttributeMaxDynamicSharedMemorySize, GSM_TOTAL);

    int n4;
    n4 = (MQ * DIM) / 4;
    cvt_hi<<<(n4 + 255) / 256, 256>>>((const float4*)text, (uint32_t*)tAhi, 1.0f, n4);
    n4 = (MK * DIM) / 4;
    cvt_hi<<<(n4 + 255) / 256, 256>>>((const float4*)vision, (uint32_t*)tVhi, 1.0f, n4);
    n4 = (3 * DIM * DIM) / 4;
    cvt_hi<<<(n4 + 255) / 256, 256>>>((const float4*)ipw, (uint32_t*)tWhi, WUP, n4);
    n4 = (DIM * DIM) / 4;
    cvt_hi<<<(n4 + 255) / 256, 256>>>((const float4*)outw, (uint32_t*)tOhi, WUP, n4);

    // Q (scaled fp16) = 0.125*(text @ Wq^T + bq)
    gemm_mma<1><<<dim3(DIM / 128, MQ / 128), 256, GSM_TOTAL>>>(
        tAhi, tWhi, ipb, nullptr, nullptr, Qhi, nullptr, MQ, DIM, DIM);
    // [K|V] fp16 = vision @ [Wk|Wv]^T + [bk|bv]
    gemm_mma<2><<<dim3(2 * DIM / 128, MK / 128), 256, GSM_TOTAL>>>(
        tVhi, tWhi + (size_t)DIM * DIM, ipb + DIM, nullptr, nullptr, Khi, Vhi, MK, 2 * DIM, DIM);
    // attention
    attn_mma<<<NB * (LQ / 32), 256, ATTN_SMEM>>>(attnw);
    // attended = ctx @ out_w^T + out_b + text
    gemm_mma<0><<<dim3(DIM / 128, MQ / 128), 256, GSM_TOTAL>>>(
        Chi, tOhi, outb, text, attp, nullptr, nullptr, MQ, DIM, DIM);
    // layernorm
    ln_kernel<<<MQ, 256>>>(attp, lng, lnb, out);
}